// round 10
// baseline (speedup 1.0000x reference)
#include <cuda_runtime.h>
#include <cuda_bf16.h>
#include <cstdint>
#include <math.h>

// MySimpleRNN: h_t = tanh(x_t@wx + h_{t-1}@wh + b), 64 steps, h_final[4096,512].
// R9: (1) input projection XZ = x@wx + b hoisted into one big parallel GEMM
//     (fp32 result; step accumulators initialize from it via LDG);
//     (2) recurrent step = K=512 GEMM with 3-stage cp.async ring, ONE barrier
//     per chunk. Split-precision bf16 mma.sync (hi*hi + hi*lo + lo*hi), fp32 acc.

#define NF 128
#define NH 512
#define TT 64
#define BMAX 4096

#define BM 128
#define BN 128
#define KC 64
#define NTHREADS 256     // 8 warps: 4(M) x 2(N), warp tile 32x64

#define STAGE_BYTES 65536u   // Ahi 16K | Alo 16K | Bhi 16K | Blo 16K
#define NSTAGE 3
#define SMEM_STEP (NSTAGE * STAGE_BYTES)
#define SMEM_XZ   (2 * STAGE_BYTES)

// ---------------- scratch (device globals; no allocation) ----------------
__device__ __align__(1024) __nv_bfloat16 g_hhi[2][(size_t)BMAX * NH];
__device__ __align__(1024) __nv_bfloat16 g_hlo[2][(size_t)BMAX * NH];
__device__ __align__(1024) __nv_bfloat16 g_xhi[TT][(size_t)BMAX * NF];
__device__ __align__(1024) __nv_bfloat16 g_xlo[TT][(size_t)BMAX * NF];
__device__ __align__(1024) __nv_bfloat16 g_wh_hi[NH * NH];   // [k][n]
__device__ __align__(1024) __nv_bfloat16 g_wh_lo[NH * NH];
__device__ __align__(1024) __nv_bfloat16 g_wx_hi[NF * NH];   // [k][n]
__device__ __align__(1024) __nv_bfloat16 g_wx_lo[NF * NH];
__device__ __align__(1024) float g_xz[(size_t)TT * BMAX * NH];  // [t][b][n], bias folded in

// ---------------- helpers ----------------
__device__ __forceinline__ uint32_t smem_u32(const void* p) {
    uint32_t a;
    asm("{ .reg .u64 t; cvta.to.shared.u64 t, %1; cvt.u32.u64 %0, t; }" : "=r"(a) : "l"(p));
    return a;
}
__device__ __forceinline__ void ldsm_x4(uint32_t* r, uint32_t addr) {
    asm volatile("ldmatrix.sync.aligned.m8n8.x4.shared.b16 {%0,%1,%2,%3}, [%4];"
                 : "=r"(r[0]), "=r"(r[1]), "=r"(r[2]), "=r"(r[3]) : "r"(addr));
}
__device__ __forceinline__ void ldsm_x4_t(uint32_t* r, uint32_t addr) {
    asm volatile("ldmatrix.sync.aligned.m8n8.x4.trans.shared.b16 {%0,%1,%2,%3}, [%4];"
                 : "=r"(r[0]), "=r"(r[1]), "=r"(r[2]), "=r"(r[3]) : "r"(addr));
}
__device__ __forceinline__ void mma16816(float* d, const uint32_t* a, const uint32_t* b) {
    asm volatile(
        "mma.sync.aligned.m16n8k16.row.col.f32.bf16.bf16.f32 "
        "{%0,%1,%2,%3}, {%4,%5,%6,%7}, {%8,%9}, {%0,%1,%2,%3};"
        : "+f"(d[0]), "+f"(d[1]), "+f"(d[2]), "+f"(d[3])
        : "r"(a[0]), "r"(a[1]), "r"(a[2]), "r"(a[3]), "r"(b[0]), "r"(b[1]));
}
__device__ __forceinline__ void cp_async16(uint32_t dst, const void* src) {
    asm volatile("cp.async.cg.shared.global [%0], [%1], 16;" :: "r"(dst), "l"(src) : "memory");
}
#define CP_COMMIT() asm volatile("cp.async.commit_group;" ::: "memory")
#define CP_WAIT(n)  asm volatile("cp.async.wait_group %0;" :: "n"(n) : "memory")

__device__ __forceinline__ uint32_t pack_bf16x2(float a, float b) {
    __nv_bfloat16 ha = __float2bfloat16(a);
    __nv_bfloat16 hb = __float2bfloat16(b);
    return ((uint32_t)__bfloat16_as_ushort(hb) << 16) | (uint32_t)__bfloat16_as_ushort(ha);
}

// Load one K=64 chunk: A[128][64] hi/lo (lda elems), B[64][128] hi/lo (ldb=NH).
__device__ __forceinline__ void load_chunk_ab(
    uint32_t sb, int tid,
    const __nv_bfloat16* gAh, const __nv_bfloat16* gAl, int lda, int kbase,
    const __nv_bfloat16* gBh, const __nv_bfloat16* gBl, int n0)
{
#pragma unroll
    for (int j = 0; j < 4; ++j) {
        int seg = j * 256 + tid;
        uint32_t row = (uint32_t)(seg >> 3);
        uint32_t ch = (uint32_t)(seg & 7);
        uint32_t off = row * 128u + ((ch ^ (row & 7u)) << 4);
        cp_async16(sb + off,          gAh + (size_t)row * lda + kbase + ch * 8);
        cp_async16(sb + 16384u + off, gAl + (size_t)row * lda + kbase + ch * 8);
    }
#pragma unroll
    for (int j = 0; j < 4; ++j) {
        int seg = j * 256 + tid;
        uint32_t kr = (uint32_t)(seg >> 4);
        uint32_t ch = (uint32_t)(seg & 15);
        uint32_t off = kr * 256u + ((ch ^ (kr & 7u)) << 4);
        cp_async16(sb + 32768u + off, gBh + (size_t)(kbase + kr) * NH + n0 + ch * 8);
        cp_async16(sb + 49152u + off, gBl + (size_t)(kbase + kr) * NH + n0 + ch * 8);
    }
    CP_COMMIT();
}

// Compute one K=64 chunk: 3-term split-precision MMA into acc[2][8][4].
__device__ __forceinline__ void compute_chunk(
    uint32_t sb, float acc[2][8][4], int wm, int wn, int lid)
{
    const uint32_t aHi = sb, aLo = sb + 16384u, bHi = sb + 32768u, bLo = sb + 49152u;
#pragma unroll
    for (int kk = 0; kk < KC / 16; ++kk) {
        const int k0 = kk * 16;
        uint32_t ah[2][4], al[2][4];
#pragma unroll
        for (int mt = 0; mt < 2; ++mt) {
            uint32_t row = (uint32_t)(wm * 32 + mt * 16 + ((lid >> 3) & 1) * 8 + (lid & 7));
            uint32_t kc = (uint32_t)((k0 >> 3) + (lid >> 4));
            uint32_t off = row * 128u + ((kc ^ (row & 7u)) << 4);
            ldsm_x4(ah[mt], aHi + off);
            ldsm_x4(al[mt], aLo + off);
        }
        uint32_t bh[8][2], bl[8][2];
#pragma unroll
        for (int np = 0; np < 4; ++np) {
            int g = lid >> 3;
            uint32_t kr = (uint32_t)(k0 + (g & 1) * 8 + (lid & 7));
            uint32_t nc = (uint32_t)(((wn * 64 + np * 16) >> 3) + (g >> 1));
            uint32_t off = kr * 256u + ((nc ^ (kr & 7u)) << 4);
            uint32_t r[4];
            ldsm_x4_t(r, bHi + off);
            bh[np * 2][0] = r[0]; bh[np * 2][1] = r[1];
            bh[np * 2 + 1][0] = r[2]; bh[np * 2 + 1][1] = r[3];
            ldsm_x4_t(r, bLo + off);
            bl[np * 2][0] = r[0]; bl[np * 2][1] = r[1];
            bl[np * 2 + 1][0] = r[2]; bl[np * 2 + 1][1] = r[3];
        }
#pragma unroll
        for (int mt = 0; mt < 2; ++mt)
#pragma unroll
            for (int nt = 0; nt < 8; ++nt) {
                mma16816(acc[mt][nt], ah[mt], bh[nt]);
                mma16816(acc[mt][nt], ah[mt], bl[nt]);
                mma16816(acc[mt][nt], al[mt], bh[nt]);
            }
    }
}

// ---------------- precompute: weight + x splits ----------------
__global__ void prep_weights(const float* __restrict__ wx, const float* __restrict__ wh) {
    int idx = blockIdx.x * blockDim.x + threadIdx.x;
    if (idx < NH * NH) {
        float v = wh[idx];
        __nv_bfloat16 hi = __float2bfloat16(v);
        g_wh_hi[idx] = hi;
        g_wh_lo[idx] = __float2bfloat16(v - __bfloat162float(hi));
    }
    if (idx < NF * NH) {
        float v = wx[idx];
        __nv_bfloat16 hi = __float2bfloat16(v);
        g_wx_hi[idx] = hi;
        g_wx_lo[idx] = __float2bfloat16(v - __bfloat162float(hi));
    }
}

__global__ void prep_x(const float* __restrict__ x, int B) {
    size_t idx = (size_t)blockIdx.x * blockDim.x + threadIdx.x;
    if (idx < (size_t)B * TT * NF) {
        int f = (int)(idx % NF);
        size_t r = idx / NF;
        int t = (int)(r % TT);
        size_t b = r / TT;
        float v = x[idx];
        __nv_bfloat16 hi = __float2bfloat16(v);
        g_xhi[t][b * NF + f] = hi;
        g_xlo[t][b * NF + f] = __float2bfloat16(v - __bfloat162float(hi));
    }
}

// ---------------- XZ GEMM: xz[t] = x_t @ wx + b (fp32); t==0 -> h1 directly ----
__global__ __launch_bounds__(NTHREADS, 1)
void xz_gemm(const float* __restrict__ bias)
{
    extern __shared__ __align__(1024) char smem[];
    const uint32_t sbase = smem_u32(smem);
    const int tid = threadIdx.x;
    const int wid = tid >> 5;
    const int lid = tid & 31;
    const int wm = wid & 3, wn = wid >> 2;
    const int m0 = blockIdx.y * BM;
    const int n0 = blockIdx.x * BN;
    const int t = blockIdx.z;

    const __nv_bfloat16* xAhi = g_xhi[t] + (size_t)m0 * NF;
    const __nv_bfloat16* xAlo = g_xlo[t] + (size_t)m0 * NF;

    float acc[2][8][4];
#pragma unroll
    for (int i = 0; i < 2; ++i)
#pragma unroll
        for (int j = 0; j < 8; ++j)
#pragma unroll
            for (int q = 0; q < 4; ++q) acc[i][j][q] = 0.0f;

    load_chunk_ab(sbase, tid, xAhi, xAlo, NF, 0, g_wx_hi, g_wx_lo, n0);
    load_chunk_ab(sbase + STAGE_BYTES, tid, xAhi, xAlo, NF, KC, g_wx_hi, g_wx_lo, n0);

    CP_WAIT(1);
    __syncthreads();
    compute_chunk(sbase, acc, wm, wn, lid);
    CP_WAIT(0);
    __syncthreads();
    compute_chunk(sbase + STAGE_BYTES, acc, wm, wn, lid);

    // epilogue: + bias; t==0 writes h1 = tanh(xz0) split; else xz fp32
    const int gq = lid >> 2, tq = lid & 3;
    float* xzout = g_xz + ((size_t)t * BMAX + m0) * NH + n0;
#pragma unroll
    for (int mt = 0; mt < 2; ++mt)
#pragma unroll
        for (int nt = 0; nt < 8; ++nt) {
            const int col = wn * 64 + nt * 8 + tq * 2;
            const float2 bv = *(const float2*)(bias + n0 + col);
            const int r0 = wm * 32 + mt * 16 + gq;
            const int r1 = r0 + 8;
            float v00 = acc[mt][nt][0] + bv.x;
            float v01 = acc[mt][nt][1] + bv.y;
            float v10 = acc[mt][nt][2] + bv.x;
            float v11 = acc[mt][nt][3] + bv.y;
            if (t == 0) {
                v00 = tanhf(v00); v01 = tanhf(v01); v10 = tanhf(v10); v11 = tanhf(v11);
                __nv_bfloat16 h00 = __float2bfloat16(v00), h01 = __float2bfloat16(v01);
                __nv_bfloat16 h10 = __float2bfloat16(v10), h11 = __float2bfloat16(v11);
                size_t o0 = (size_t)(m0 + r0) * NH + n0 + col;
                size_t o1 = (size_t)(m0 + r1) * NH + n0 + col;
                *(uint32_t*)&g_hhi[0][o0] =
                    ((uint32_t)__bfloat16_as_ushort(h01) << 16) | (uint32_t)__bfloat16_as_ushort(h00);
                *(uint32_t*)&g_hhi[0][o1] =
                    ((uint32_t)__bfloat16_as_ushort(h11) << 16) | (uint32_t)__bfloat16_as_ushort(h10);
                *(uint32_t*)&g_hlo[0][o0] = pack_bf16x2(v00 - __bfloat162float(h00), v01 - __bfloat162float(h01));
                *(uint32_t*)&g_hlo[0][o1] = pack_bf16x2(v10 - __bfloat162float(h10), v11 - __bfloat162float(h11));
            } else {
                *(float2*)(xzout + (size_t)r0 * NH + col) = make_float2(v00, v01);
                *(float2*)(xzout + (size_t)r1 * NH + col) = make_float2(v10, v11);
            }
        }
}

// ---------------- recurrent step: h_t = tanh(xz_t + h_{t-1}@wh) ----------------
__global__ __launch_bounds__(NTHREADS, 1)
void rnn_step_mma(float* __restrict__ dout, int t)
{
    extern __shared__ __align__(1024) char smem[];
    const uint32_t sbase = smem_u32(smem);
    const int tid = threadIdx.x;
    const int wid = tid >> 5;
    const int lid = tid & 31;
    const int wm = wid & 3, wn = wid >> 2;
    const int m0 = blockIdx.y * BM;
    const int n0 = blockIdx.x * BN;
    const int src = (t + 1) & 1;

    const __nv_bfloat16* hAhi = g_hhi[src] + (size_t)m0 * NH;
    const __nv_bfloat16* hAlo = g_hlo[src] + (size_t)m0 * NH;

    load_chunk_ab(sbase, tid, hAhi, hAlo, NH, 0, g_wh_hi, g_wh_lo, n0);
    load_chunk_ab(sbase + STAGE_BYTES, tid, hAhi, hAlo, NH, KC, g_wh_hi, g_wh_lo, n0);

    // acc init from xz[t] (overlaps with the chunk loads in flight)
    const int gq = lid >> 2, tq = lid & 3;
    float acc[2][8][4];
    {
        const float* xz = g_xz + ((size_t)t * BMAX + m0) * NH + n0;
#pragma unroll
        for (int mt = 0; mt < 2; ++mt)
#pragma unroll
            for (int nt = 0; nt < 8; ++nt) {
                const int col = wn * 64 + nt * 8 + tq * 2;
                const int r0 = wm * 32 + mt * 16 + gq;
                float2 a = *(const float2*)(xz + (size_t)r0 * NH + col);
                float2 bb = *(const float2*)(xz + (size_t)(r0 + 8) * NH + col);
                acc[mt][nt][0] = a.x;  acc[mt][nt][1] = a.y;
                acc[mt][nt][2] = bb.x; acc[mt][nt][3] = bb.y;
            }
    }

    // 8 chunks over K=512, 3-stage ring, one barrier per chunk
#pragma unroll 1
    for (int i = 0; i < NH / KC; ++i) {
        if (i + 1 < NH / KC) CP_WAIT(1); else CP_WAIT(0);
        __syncthreads();
        if (i + 2 < NH / KC)
            load_chunk_ab(sbase + (uint32_t)((i + 2) % NSTAGE) * STAGE_BYTES, tid,
                          hAhi, hAlo, NH, (i + 2) * KC, g_wh_hi, g_wh_lo, n0);
        compute_chunk(sbase + (uint32_t)(i % NSTAGE) * STAGE_BYTES, acc, wm, wn, lid);
    }

    // epilogue: tanh; split to bf16 hi/lo, or fp32 out at t=63
    const bool last = (t == TT - 1);
    const int dst = t & 1;
#pragma unroll
    for (int mt = 0; mt < 2; ++mt)
#pragma unroll
        for (int nt = 0; nt < 8; ++nt) {
            const int col = n0 + wn * 64 + nt * 8 + tq * 2;
            const int r0 = m0 + wm * 32 + mt * 16 + gq;
            const int r1 = r0 + 8;
            float v00 = tanhf(acc[mt][nt][0]);
            float v01 = tanhf(acc[mt][nt][1]);
            float v10 = tanhf(acc[mt][nt][2]);
            float v11 = tanhf(acc[mt][nt][3]);
            if (last) {
                *(float2*)(dout + (size_t)r0 * NH + col) = make_float2(v00, v01);
                *(float2*)(dout + (size_t)r1 * NH + col) = make_float2(v10, v11);
            } else {
                __nv_bfloat16 h00 = __float2bfloat16(v00), h01 = __float2bfloat16(v01);
                __nv_bfloat16 h10 = __float2bfloat16(v10), h11 = __float2bfloat16(v11);
                *(uint32_t*)&g_hhi[dst][(size_t)r0 * NH + col] =
                    ((uint32_t)__bfloat16_as_ushort(h01) << 16) | (uint32_t)__bfloat16_as_ushort(h00);
                *(uint32_t*)&g_hhi[dst][(size_t)r1 * NH + col] =
                    ((uint32_t)__bfloat16_as_ushort(h11) << 16) | (uint32_t)__bfloat16_as_ushort(h10);
                *(uint32_t*)&g_hlo[dst][(size_t)r0 * NH + col] =
                    pack_bf16x2(v00 - __bfloat162float(h00), v01 - __bfloat162float(h01));
                *(uint32_t*)&g_hlo[dst][(size_t)r1 * NH + col] =
                    pack_bf16x2(v10 - __bfloat162float(h10), v11 - __bfloat162float(h11));
            }
        }
}

// ---------------- launch ----------------
extern "C" void kernel_launch(void* const* d_in, const int* in_sizes, int n_in,
                              void* d_out, int out_size)
{
    const float* x  = (const float*)d_in[0];  // [B, 64, 128]
    const float* wx = (const float*)d_in[1];  // [128, 512]
    const float* wh = (const float*)d_in[2];  // [512, 512]
    const float* b  = (const float*)d_in[3];  // [1, 512]
    float* out = (float*)d_out;               // [B, 512]

    const int B = in_sizes[0] / (TT * NF);    // 4096

    cudaFuncSetAttribute(xz_gemm, cudaFuncAttributeMaxDynamicSharedMemorySize, SMEM_XZ);
    cudaFuncSetAttribute(rnn_step_mma, cudaFuncAttributeMaxDynamicSharedMemorySize, SMEM_STEP);

    prep_weights<<<(NH * NH + 255) / 256, 256>>>(wx, wh);
    {
        size_t n = (size_t)B * TT * NF;
        prep_x<<<(unsigned)((n + 255) / 256), 256>>>(x, B);
    }

    dim3 gridxz(NH / BN, B / BM, TT);         // (4, 32, 64) = 8192 CTAs
    xz_gemm<<<gridxz, NTHREADS, SMEM_XZ>>>(b);

    dim3 grid(NH / BN, B / BM);               // (4, 32) = 128 CTAs
    for (int t = 1; t < TT; ++t) {
        rnn_step_mma<<<grid, NTHREADS, SMEM_STEP>>>(out, t);
    }
}